// round 16
// baseline (speedup 1.0000x reference)
#include <cuda_runtime.h>
#include <cuda_fp16.h>
#include <math.h>
#include <stdint.h>

#define BATCH 4
#define SEQ   2048
#define DMODEL 512
#define NHEADS 8
#define HDIM  64
#define FFDIM 2048
#define MROWS (BATCH * SEQ)
#define QKVN  (3 * DMODEL)

// ------------------------- scratch (device globals) -------------------------
__device__ __half g_x16  [MROWS * DMODEL];
__device__ __half g_qkv16[MROWS * QKVN];
__device__ __half g_ctx16[MROWS * DMODEL];
__device__ __half g_x1h  [MROWS * DMODEL];
__device__ __half g_h16  [MROWS * FFDIM];
__device__ float  g_y1   [MROWS * DMODEL];
__device__ float  g_x1   [MROWS * DMODEL];
__device__ __half g_wqkv16[QKVN * DMODEL];
__device__ __half g_wo16  [DMODEL * DMODEL];
__device__ __half g_w1_16 [FFDIM * DMODEL];
__device__ __half g_w2_16 [DMODEL * FFDIM];

// ------------------------- PTX helpers -------------------------
__device__ __forceinline__ uint32_t smem_u32(const void* p) {
    uint32_t a;
    asm("{ .reg .u64 t; cvta.to.shared.u64 t, %1; cvt.u32.u64 %0, t; }" : "=r"(a) : "l"(p));
    return a;
}
#define CPA16(s, g)  asm volatile("cp.async.cg.shared.global [%0], [%1], 16;" :: "r"(s), "l"(g))
#define CPA_COMMIT() asm volatile("cp.async.commit_group;" ::: "memory")
#define CPA_WAIT(n)  asm volatile("cp.async.wait_group %0;" :: "n"(n) : "memory")

__device__ __forceinline__ void ldsm4(uint32_t& r0, uint32_t& r1, uint32_t& r2, uint32_t& r3, uint32_t a) {
    asm volatile("ldmatrix.sync.aligned.m8n8.x4.shared.b16 {%0,%1,%2,%3}, [%4];"
                 : "=r"(r0), "=r"(r1), "=r"(r2), "=r"(r3) : "r"(a));
}
__device__ __forceinline__ void ldsm4t(uint32_t& r0, uint32_t& r1, uint32_t& r2, uint32_t& r3, uint32_t a) {
    asm volatile("ldmatrix.sync.aligned.m8n8.x4.trans.shared.b16 {%0,%1,%2,%3}, [%4];"
                 : "=r"(r0), "=r"(r1), "=r"(r2), "=r"(r3) : "r"(a));
}
__device__ __forceinline__ void mma16816(float* c, const uint32_t* a, const uint32_t* b) {
    asm volatile("mma.sync.aligned.m16n8k16.row.col.f32.f16.f16.f32 "
                 "{%0,%1,%2,%3},{%4,%5,%6,%7},{%8,%9},{%0,%1,%2,%3};"
                 : "+f"(c[0]), "+f"(c[1]), "+f"(c[2]), "+f"(c[3])
                 : "r"(a[0]), "r"(a[1]), "r"(a[2]), "r"(a[3]), "r"(b[0]), "r"(b[1]));
}
__device__ __forceinline__ void mma16816h(uint32_t* c, const uint32_t* a, const uint32_t* b) {
    asm volatile("mma.sync.aligned.m16n8k16.row.col.f16.f16.f16.f16 "
                 "{%0,%1},{%2,%3,%4,%5},{%6,%7},{%0,%1};"
                 : "+r"(c[0]), "+r"(c[1])
                 : "r"(a[0]), "r"(a[1]), "r"(a[2]), "r"(a[3]), "r"(b[0]), "r"(b[1]));
}
__device__ __forceinline__ uint32_t packh2(float a, float b) {
    __half2 h = __floats2half2_rn(a, b);
    return *(uint32_t*)&h;
}
__device__ __forceinline__ uint32_t ex2_h2(uint32_t a) {
    uint32_t d;
    asm("ex2.approx.f16x2 %0, %1;" : "=r"(d) : "r"(a));
    return d;
}
__device__ __forceinline__ uint32_t min_h2(uint32_t a, uint32_t b) {
    uint32_t d;
    asm("min.f16x2 %0, %1, %2;" : "=r"(d) : "r"(a), "r"(b));
    return d;
}
__device__ __forceinline__ uint32_t add_h2(uint32_t a, uint32_t b) {
    uint32_t d;
    asm("add.rn.f16x2 %0, %1, %2;" : "=r"(d) : "r"(a), "r"(b));
    return d;
}
__device__ __forceinline__ uint32_t mul_h2(uint32_t a, uint32_t b) {
    uint32_t d;
    asm("mul.f16x2 %0, %1, %2;" : "=r"(d) : "r"(a), "r"(b));
    return d;
}

// ======================= HMMA fp16 GEMM (R5 winner, verbatim) =======================
#define G_STRIDE 40
#define G_ASTG   (256 * G_STRIDE)
#define G_BSTG   (128 * G_STRIDE)
#define G_STAGE  (G_ASTG + G_BSTG)
#define G_SMEM   (4 * G_STAGE * 2)

template<bool RELU, bool RES, bool OUTF, bool OUTH>
__global__ __launch_bounds__(256, 1)
void gemm_hmma(const __half* __restrict__ A, const __half* __restrict__ B,
               const float* __restrict__ bias, const float* __restrict__ Rres,
               float* __restrict__ Cf, __half* __restrict__ Ch, int M, int N, int K)
{
    extern __shared__ __half smh[];
    const uint32_t sbase = smem_u32(smh);
    const int tid = threadIdx.x, wid = tid >> 5, lane = tid & 31;
    const int m0 = blockIdx.y * 256, n0 = blockIdx.x * 128;
    const int wm = (wid & 3) * 64, wn = (wid >> 2) * 64;

    float acc[4][8][4];
#pragma unroll
    for (int i = 0; i < 4; i++)
#pragma unroll
        for (int j = 0; j < 8; j++)
#pragma unroll
            for (int e = 0; e < 4; e++) acc[i][j][e] = 0.f;

    const int arow = tid >> 2;
    const int ac   = tid & 3;

    auto load_stage = [&](int kt, int s) {
        const uint32_t sa = sbase + s * G_STAGE * 2;
        const uint32_t sb = sa + G_ASTG * 2;
        const __half* ag = A + (size_t)(m0 + arow) * K + kt * 32 + ac * 8;
#pragma unroll
        for (int i = 0; i < 4; i++) {
            const int row = arow + i * 64;
            CPA16(sa + (row * G_STRIDE + ac * 8) * 2, ag + (size_t)(i * 64) * K);
        }
        const __half* bg = B + (size_t)(n0 + arow) * K + kt * 32 + ac * 8;
#pragma unroll
        for (int i = 0; i < 2; i++) {
            const int row = arow + i * 64;
            CPA16(sb + (row * G_STRIDE + ac * 8) * 2, bg + (size_t)(i * 64) * K);
        }
        CPA_COMMIT();
    };

    const int KT = K >> 5;
    load_stage(0, 0);
    load_stage(1, 1);

    const int aRow = lane & 15, aSel = (lane >> 4) * 8;
    const int bN   = ((lane >> 4) << 3) + (lane & 7);
    const int bSel = ((lane >> 3) & 1) * 8;

    for (int kt = 0; kt < KT; ++kt) {
        const int s = kt & 3;
        if (kt + 2 < KT) {
            load_stage(kt + 2, (kt + 2) & 3);
            CPA_WAIT(2);
        } else if (kt + 1 < KT) {
            CPA_WAIT(1);
        } else {
            CPA_WAIT(0);
        }
        __syncthreads();

        const uint32_t sa0 = sbase + s * G_STAGE * 2;
        const uint32_t sb0 = sa0 + G_ASTG * 2;
#pragma unroll
        for (int ks = 0; ks < 2; ks++) {
            uint32_t a[4][4], b[8][2];
#pragma unroll
            for (int mi = 0; mi < 4; mi++)
                ldsm4(a[mi][0], a[mi][1], a[mi][2], a[mi][3],
                      sa0 + ((wm + mi * 16 + aRow) * G_STRIDE + ks * 16 + aSel) * 2);
#pragma unroll
            for (int nb = 0; nb < 4; nb++) {
                uint32_t r0, r1, r2, r3;
                ldsm4(r0, r1, r2, r3,
                      sb0 + ((wn + nb * 16 + bN) * G_STRIDE + ks * 16 + bSel) * 2);
                b[2 * nb][0] = r0; b[2 * nb][1] = r1;
                b[2 * nb + 1][0] = r2; b[2 * nb + 1][1] = r3;
            }
#pragma unroll
            for (int mi = 0; mi < 4; mi++)
#pragma unroll
                for (int ni = 0; ni < 8; ni++)
                    mma16816(acc[mi][ni], a[mi], b[ni]);
        }
    }

    const int r0 = lane >> 2, c0 = (lane & 3) * 2;
#pragma unroll
    for (int ni = 0; ni < 8; ni++) {
        const int col = n0 + wn + ni * 8 + c0;
        const float2 bv = *(const float2*)(bias + col);
#pragma unroll
        for (int mi = 0; mi < 4; mi++) {
            const int gr0 = m0 + wm + mi * 16 + r0;
            float v0 = acc[mi][ni][0] + bv.x;
            float v1 = acc[mi][ni][1] + bv.y;
            float v2 = acc[mi][ni][2] + bv.x;
            float v3 = acc[mi][ni][3] + bv.y;
            if (RES) {
                float2 ra = *(const float2*)(Rres + (size_t)gr0 * N + col);
                float2 rb = *(const float2*)(Rres + (size_t)(gr0 + 8) * N + col);
                v0 += ra.x; v1 += ra.y; v2 += rb.x; v3 += rb.y;
            }
            if (RELU) {
                v0 = fmaxf(v0, 0.f); v1 = fmaxf(v1, 0.f);
                v2 = fmaxf(v2, 0.f); v3 = fmaxf(v3, 0.f);
            }
            if (OUTF) {
                float2 o0; o0.x = v0; o0.y = v1;
                float2 o1; o1.x = v2; o1.y = v3;
                *(float2*)(Cf + (size_t)gr0 * N + col) = o0;
                *(float2*)(Cf + (size_t)(gr0 + 8) * N + col) = o1;
            }
            if (OUTH) {
                *(uint32_t*)(Ch + (size_t)gr0 * N + col) = packh2(v0, v1);
                *(uint32_t*)(Ch + (size_t)(gr0 + 8) * N + col) = packh2(v2, v3);
            }
        }
    }
}

// ===== Flash attention (R14/R11 verbatim: f16-acc S, f16x2 softmax, l via ones-MMA) =====
#define A_STRIDE 72
#define AT_QMAT  (128 * A_STRIDE)
#define AT_KMAT  (64 * A_STRIDE)
#define A_QOFF   0
#define A_KOFF   AT_QMAT
#define A_VOFF   (AT_QMAT + 2 * AT_KMAT)
#define A_SMEM   ((AT_QMAT + 4 * AT_KMAT) * 2)   // 55296 bytes

__global__ __launch_bounds__(256, 2)
void attn_hmma(const __half* __restrict__ qkv, __half* __restrict__ ctx)
{
    extern __shared__ __half smh[];
    const uint32_t sbase = smem_u32(smh);
    const int tid = threadIdx.x, wid = tid >> 5, lane = tid & 31;
    const int qt = gridDim.x - 1 - blockIdx.x;
    const int h = blockIdx.y, b = blockIdx.z;
    const int q0 = qt * 128;

    const __half* qg = qkv + ((size_t)b * SEQ + q0) * QKVN + h * HDIM;
    const __half* kg = qkv + (size_t)b * SEQ * QKVN + DMODEL + h * HDIM;
    const __half* vg = kg + DMODEL;

#pragma unroll
    for (int i = 0; i < 4; i++) {
        int id = tid + i * 256;
        int row = id >> 3, c = id & 7;
        CPA16(sbase + (A_QOFF + row * A_STRIDE + c * 8) * 2, qg + (size_t)row * QKVN + c * 8);
    }
    auto loadKV = [&](int t, int u) {
        const __half* kt_ = kg + (size_t)(t * 64) * QKVN;
        const __half* vt_ = vg + (size_t)(t * 64) * QKVN;
#pragma unroll
        for (int i = 0; i < 2; i++) {
            int id = tid + i * 256;
            int row = id >> 3, c = id & 7;
            CPA16(sbase + (A_KOFF + u * AT_KMAT + row * A_STRIDE + c * 8) * 2, kt_ + (size_t)row * QKVN + c * 8);
            CPA16(sbase + (A_VOFF + u * AT_KMAT + row * A_STRIDE + c * 8) * 2, vt_ + (size_t)row * QKVN + c * 8);
        }
        CPA_COMMIT();
    };
    loadKV(0, 0);

    uint32_t aQ[4][4];
    float accO[8][4];
    float accL[4];
#pragma unroll
    for (int j = 0; j < 8; j++)
#pragma unroll
        for (int e = 0; e < 4; e++) accO[j][e] = 0.f;
#pragma unroll
    for (int e = 0; e < 4; e++) accL[e] = 0.f;

    const int r0 = lane >> 2, c0 = (lane & 3) * 2;
    const int aRow = lane & 15, aSel = (lane >> 4) * 8;
    const int bN   = ((lane >> 4) << 3) + (lane & 7);
    const int bSel = ((lane >> 3) & 1) * 8;
    const int vK   = (lane & 7) + ((lane >> 3) & 1) * 8;
    const int vN   = (lane >> 4) * 8;

    const uint32_t CLAMP = 0x4B804B80u;                        // f16x2 {15, 15}
    const uint32_t SCLQ  = packh2(0.18033688f, 0.18033688f);   // 0.125 * log2(e)
    const uint32_t NEGINF_LO = 0x0000FC00u;
    const uint32_t NEGINF_HI = 0xFC000000u;
    uint32_t bOnes[2];
    bOnes[0] = 0x3C003C00u; bOnes[1] = 0x3C003C00u;

    const int nt = 2 * qt + 2;
    for (int t = 0; t < nt; t++) {
        const int u = t & 1;
        __syncthreads();
        if (t + 1 < nt) {
            loadKV(t + 1, (t + 1) & 1);
            CPA_WAIT(1);
        } else {
            CPA_WAIT(0);
        }
        __syncthreads();

        if (t == 0) {
#pragma unroll
            for (int ks = 0; ks < 4; ks++) {
                ldsm4(aQ[ks][0], aQ[ks][1], aQ[ks][2], aQ[ks][3],
                      sbase + (A_QOFF + (wid * 16 + aRow) * A_STRIDE + ks * 16 + aSel) * 2);
#pragma unroll
                for (int e = 0; e < 4; e++) aQ[ks][e] = mul_h2(aQ[ks][e], SCLQ);
            }
        }

        uint32_t scP[8][2];
#pragma unroll
        for (int j = 0; j < 8; j++) { scP[j][0] = 0u; scP[j][1] = 0u; }

        const uint32_t kb = sbase + (A_KOFF + u * AT_KMAT) * 2;
#pragma unroll
        for (int ks = 0; ks < 4; ks++) {
            uint32_t bK[8][2];
#pragma unroll
            for (int nb = 0; nb < 4; nb++) {
                uint32_t x0, x1, x2, x3;
                ldsm4(x0, x1, x2, x3, kb + ((nb * 16 + bN) * A_STRIDE + ks * 16 + bSel) * 2);
                bK[2 * nb][0] = x0; bK[2 * nb][1] = x1;
                bK[2 * nb + 1][0] = x2; bK[2 * nb + 1][1] = x3;
            }
#pragma unroll
            for (int j = 0; j < 8; j++)
                mma16816h(scP[j], aQ[ks], bK[j]);
        }

        if (t >= 2 * qt) {
            const int rg0 = q0 + wid * 16 + r0;
#pragma unroll
            for (int j = 0; j < 8; j++) {
                const int kcol = t * 64 + j * 8 + c0;
                uint32_t m0 = (kcol > rg0 ? NEGINF_LO : 0u) | (kcol + 1 > rg0 ? NEGINF_HI : 0u);
                uint32_t m1 = (kcol > rg0 + 8 ? NEGINF_LO : 0u) | (kcol + 1 > rg0 + 8 ? NEGINF_HI : 0u);
                if (m0) scP[j][0] = add_h2(scP[j][0], m0);
                if (m1) scP[j][1] = add_h2(scP[j][1], m1);
            }
        }

#pragma unroll
        for (int j = 0; j < 8; j++) {
            scP[j][0] = ex2_h2(min_h2(scP[j][0], CLAMP));
            scP[j][1] = ex2_h2(min_h2(scP[j][1], CLAMP));
        }

        const uint32_t vb = sbase + (A_VOFF + u * AT_KMAT) * 2;
#pragma unroll
        for (int k2 = 0; k2 < 4; k2++) {
            uint32_t aP[4];
            aP[0] = scP[2 * k2][0];     aP[1] = scP[2 * k2][1];
            aP[2] = scP[2 * k2 + 1][0]; aP[3] = scP[2 * k2 + 1][1];
            uint32_t bV[8][2];
#pragma unroll
            for (int nb = 0; nb < 4; nb++) {
                uint32_t x0, x1, x2, x3;
                ldsm4t(x0, x1, x2, x3, vb + ((k2 * 16 + vK) * A_STRIDE + nb * 16 + vN) * 2);
                bV[2 * nb][0] = x0; bV[2 * nb][1] = x1;
                bV[2 * nb + 1][0] = x2; bV[2 * nb + 1][1] = x3;
            }
#pragma unroll
            for (int j = 0; j < 8; j++)
                mma16816(accO[j], aP, bV[j]);
            mma16816(accL, aP, bOnes);
        }
    }

    const float inv0 = 1.f / accL[0], inv1 = 1.f / accL[2];
    const size_t grow = (size_t)b * SEQ + q0 + wid * 16 + r0;
#pragma unroll
    for (int j = 0; j < 8; j++) {
        const int col = h * HDIM + j * 8 + c0;
        *(uint32_t*)(ctx + grow * DMODEL + col)       = packh2(accO[j][0] * inv0, accO[j][1] * inv0);
        *(uint32_t*)(ctx + (grow + 8) * DMODEL + col) = packh2(accO[j][2] * inv1, accO[j][3] * inv1);
    }
}

// ======================= fp32 -> fp16 convert (up to 3 tensors per launch) =======================
__global__ __launch_bounds__(256)
void f2h_tri(const float* __restrict__ s0, __half* __restrict__ d0, int n0,
             const float* __restrict__ s1, __half* __restrict__ d1, int n1,
             const float* __restrict__ s2, __half* __restrict__ d2, int n2)
{
    int i = blockIdx.x * 256 + threadIdx.x;
    const float* s; __half* d;
    if (i < n0)      { s = s0; d = d0; }
    else if ((i -= n0) < n1) { s = s1; d = d1; }
    else if ((i -= n1) < n2) { s = s2; d = d2; }
    else return;
    float4 v = ((const float4*)s)[i];
    ((uint32_t*)d)[2 * i]     = packh2(v.x, v.y);
    ((uint32_t*)d)[2 * i + 1] = packh2(v.z, v.w);
}

// ======================= LayerNorm: one warp per row, no smem, no barriers ==============
template<bool OUTH>
__global__ __launch_bounds__(256)
void ln_kernel(const float* __restrict__ y, const float* __restrict__ g,
               const float* __restrict__ b, float* __restrict__ out, __half* __restrict__ oh)
{
    const int wid = threadIdx.x >> 5, lane = threadIdx.x & 31;
    const int row = blockIdx.x * 8 + wid;

    const float* yr = y + (size_t)row * DMODEL;
    float4 v[4];
#pragma unroll
    for (int c = 0; c < 4; c++)
        v[c] = *(const float4*)(yr + c * 128 + lane * 4);

    float s = 0.f;
#pragma unroll
    for (int c = 0; c < 4; c++) s += v[c].x + v[c].y + v[c].z + v[c].w;
#pragma unroll
    for (int o = 16; o; o >>= 1) s += __shfl_xor_sync(0xffffffffu, s, o);
    const float mu = s * (1.f / DMODEL);

    float q = 0.f;
#pragma unroll
    for (int c = 0; c < 4; c++) {
        v[c].x -= mu; v[c].y -= mu; v[c].z -= mu; v[c].w -= mu;
        q += v[c].x * v[c].x + v[c].y * v[c].y + v[c].z * v[c].z + v[c].w * v[c].w;
    }
#pragma unroll
    for (int o = 16; o; o >>= 1) q += __shfl_xor_sync(0xffffffffu, q, o);
    const float r = rsqrtf(q * (1.f / DMODEL) + 1e-5f);

#pragma unroll
    for (int c = 0; c < 4; c++) {
        const int col = c * 128 + lane * 4;
        float4 gg = *(const float4*)(g + col);
        float4 bb = *(const float4*)(b + col);
        float o0 = v[c].x * r * gg.x + bb.x;
        float o1 = v[c].y * r * gg.y + bb.y;
        float o2 = v[c].z * r * gg.z + bb.z;
        float o3 = v[c].w * r * gg.w + bb.w;
        float4 ov; ov.x = o0; ov.y = o1; ov.z = o2; ov.w = o3;
        *(float4*)(out + (size_t)row * DMODEL + col) = ov;
        if (OUTH) {
            size_t ofs = (size_t)row * DMODEL + col;
            *(uint32_t*)(oh + ofs)     = packh2(o0, o1);
            *(uint32_t*)(oh + ofs + 2) = packh2(o2, o3);
        }
    }
}

// =================================== launch ===================================
extern "C" void kernel_launch(void* const* d_in, const int* in_sizes, int n_in,
                              void* d_out, int out_size)
{
    const float* x    = (const float*)d_in[0];
    const float* Wqkv = (const float*)d_in[1];
    const float* bqkv = (const float*)d_in[2];
    const float* Wo   = (const float*)d_in[3];
    const float* bo   = (const float*)d_in[4];
    const float* W1   = (const float*)d_in[5];
    const float* b1   = (const float*)d_in[6];
    const float* W2   = (const float*)d_in[7];
    const float* b2   = (const float*)d_in[8];
    const float* g1   = (const float*)d_in[9];
    const float* bn1  = (const float*)d_in[10];
    const float* g2   = (const float*)d_in[11];
    const float* bn2  = (const float*)d_in[12];
    float* out = (float*)d_out;

    __half *p_x16, *p_qkv16, *p_ctx16, *p_x1h, *p_h16;
    __half *p_wqkv, *p_wo, *p_w1, *p_w2;
    float *p_y1, *p_x1;
    cudaGetSymbolAddress((void**)&p_x16,   g_x16);
    cudaGetSymbolAddress((void**)&p_qkv16, g_qkv16);
    cudaGetSymbolAddress((void**)&p_ctx16, g_ctx16);
    cudaGetSymbolAddress((void**)&p_x1h,   g_x1h);
    cudaGetSymbolAddress((void**)&p_h16,   g_h16);
    cudaGetSymbolAddress((void**)&p_y1,    g_y1);
    cudaGetSymbolAddress((void**)&p_x1,    g_x1);
    cudaGetSymbolAddress((void**)&p_wqkv,  g_wqkv16);
    cudaGetSymbolAddress((void**)&p_wo,    g_wo16);
    cudaGetSymbolAddress((void**)&p_w1,    g_w1_16);
    cudaGetSymbolAddress((void**)&p_w2,    g_w2_16);

    cudaFuncSetAttribute(gemm_hmma<false, false, false, true>, cudaFuncAttributeMaxDynamicSharedMemorySize, G_SMEM);
    cudaFuncSetAttribute(gemm_hmma<false, true,  true,  false>, cudaFuncAttributeMaxDynamicSharedMemorySize, G_SMEM);
    cudaFuncSetAttribute(gemm_hmma<true,  false, false, true>, cudaFuncAttributeMaxDynamicSharedMemorySize, G_SMEM);
    cudaFuncSetAttribute(attn_hmma, cudaFuncAttributeMaxDynamicSharedMemorySize, A_SMEM);

    const int M = MROWS;
    const int c0 = M * DMODEL / 4, c1 = QKVN * DMODEL / 4, c2 = DMODEL * DMODEL / 4;
    const int c3 = FFDIM * DMODEL / 4, c4 = DMODEL * FFDIM / 4;

    // [0] x + Wqkv -> fp16
    f2h_tri<<<(c0 + c1 + 255) / 256, 256>>>(x, p_x16, c0, Wqkv, p_wqkv, c1, nullptr, nullptr, 0);
    // [1] Wo + W1 + W2 -> fp16
    f2h_tri<<<(c2 + c3 + c4 + 255) / 256, 256>>>(Wo, p_wo, c2, W1, p_w1, c3, W2, p_w2, c4);

    // [2] QKV projection -> qkv fp16
    gemm_hmma<false, false, false, true><<<dim3(QKVN / 128, M / 256), 256, G_SMEM>>>(
        p_x16, p_wqkv, bqkv, nullptr, nullptr, p_qkv16, M, QKVN, DMODEL);

    // [3] causal flash attention -> ctx fp16  [ncu capture slot]
    attn_hmma<<<dim3(SEQ / 128, NHEADS, BATCH), 256, A_SMEM>>>(p_qkv16, p_ctx16);

    // [4] out proj + residual(x) -> y1 fp32
    gemm_hmma<false, true, true, false><<<dim3(DMODEL / 128, M / 256), 256, G_SMEM>>>(
        p_ctx16, p_wo, bo, x, p_y1, nullptr, M, DMODEL, DMODEL);

    // [5] LN1 -> x1 fp32 + fp16
    ln_kernel<true><<<M / 8, 256>>>(p_y1, g1, bn1, p_x1, p_x1h);

    // [6] FFN up + ReLU -> h fp16
    gemm_hmma<true, false, false, true><<<dim3(FFDIM / 128, M / 256), 256, G_SMEM>>>(
        p_x1h, p_w1, b1, nullptr, nullptr, p_h16, M, FFDIM, DMODEL);

    // [7] FFN down + residual(x1) -> y1 fp32
    gemm_hmma<false, true, true, false><<<dim3(DMODEL / 128, M / 256), 256, G_SMEM>>>(
        p_h16, p_w2, b2, p_x1, p_y1, nullptr, M, DMODEL, FFDIM);

    // [8] LN2 -> out
    ln_kernel<false><<<M / 8, 256>>>(p_y1, g2, bn2, out, nullptr);
}

// round 17
// speedup vs baseline: 1.0071x; 1.0071x over previous
#include <cuda_runtime.h>
#include <cuda_fp16.h>
#include <math.h>
#include <stdint.h>

#define BATCH 4
#define SEQ   2048
#define DMODEL 512
#define NHEADS 8
#define HDIM  64
#define FFDIM 2048
#define MROWS (BATCH * SEQ)
#define QKVN  (3 * DMODEL)

// ------------------------- scratch (device globals) -------------------------
__device__ __half g_x16  [MROWS * DMODEL];
__device__ __half g_qkv16[MROWS * QKVN];
__device__ __half g_ctx16[MROWS * DMODEL];
__device__ __half g_x1h  [MROWS * DMODEL];
__device__ __half g_h16  [MROWS * FFDIM];
__device__ float  g_y1   [MROWS * DMODEL];
__device__ float  g_x1   [MROWS * DMODEL];
__device__ __half g_wqkv16[QKVN * DMODEL];
__device__ __half g_wo16  [DMODEL * DMODEL];
__device__ __half g_w1_16 [FFDIM * DMODEL];
__device__ __half g_w2_16 [DMODEL * FFDIM];

// ------------------------- PTX helpers -------------------------
__device__ __forceinline__ uint32_t smem_u32(const void* p) {
    uint32_t a;
    asm("{ .reg .u64 t; cvta.to.shared.u64 t, %1; cvt.u32.u64 %0, t; }" : "=r"(a) : "l"(p));
    return a;
}
#define CPA16(s, g)  asm volatile("cp.async.cg.shared.global [%0], [%1], 16;" :: "r"(s), "l"(g))
#define CPA_COMMIT() asm volatile("cp.async.commit_group;" ::: "memory")
#define CPA_WAIT(n)  asm volatile("cp.async.wait_group %0;" :: "n"(n) : "memory")

__device__ __forceinline__ void ldsm4(uint32_t& r0, uint32_t& r1, uint32_t& r2, uint32_t& r3, uint32_t a) {
    asm volatile("ldmatrix.sync.aligned.m8n8.x4.shared.b16 {%0,%1,%2,%3}, [%4];"
                 : "=r"(r0), "=r"(r1), "=r"(r2), "=r"(r3) : "r"(a));
}
__device__ __forceinline__ void ldsm4t(uint32_t& r0, uint32_t& r1, uint32_t& r2, uint32_t& r3, uint32_t a) {
    asm volatile("ldmatrix.sync.aligned.m8n8.x4.trans.shared.b16 {%0,%1,%2,%3}, [%4];"
                 : "=r"(r0), "=r"(r1), "=r"(r2), "=r"(r3) : "r"(a));
}
__device__ __forceinline__ void mma16816(float* c, const uint32_t* a, const uint32_t* b) {
    asm volatile("mma.sync.aligned.m16n8k16.row.col.f32.f16.f16.f32 "
                 "{%0,%1,%2,%3},{%4,%5,%6,%7},{%8,%9},{%0,%1,%2,%3};"
                 : "+f"(c[0]), "+f"(c[1]), "+f"(c[2]), "+f"(c[3])
                 : "r"(a[0]), "r"(a[1]), "r"(a[2]), "r"(a[3]), "r"(b[0]), "r"(b[1]));
}
__device__ __forceinline__ void mma16816h(uint32_t* c, const uint32_t* a, const uint32_t* b) {
    asm volatile("mma.sync.aligned.m16n8k16.row.col.f16.f16.f16.f16 "
                 "{%0,%1},{%2,%3,%4,%5},{%6,%7},{%0,%1};"
                 : "+r"(c[0]), "+r"(c[1])
                 : "r"(a[0]), "r"(a[1]), "r"(a[2]), "r"(a[3]), "r"(b[0]), "r"(b[1]));
}
__device__ __forceinline__ uint32_t packh2(float a, float b) {
    __half2 h = __floats2half2_rn(a, b);
    return *(uint32_t*)&h;
}
__device__ __forceinline__ uint32_t ex2_h2(uint32_t a) {
    uint32_t d;
    asm("ex2.approx.f16x2 %0, %1;" : "=r"(d) : "r"(a));
    return d;
}
__device__ __forceinline__ uint32_t min_h2(uint32_t a, uint32_t b) {
    uint32_t d;
    asm("min.f16x2 %0, %1, %2;" : "=r"(d) : "r"(a), "r"(b));
    return d;
}
__device__ __forceinline__ uint32_t add_h2(uint32_t a, uint32_t b) {
    uint32_t d;
    asm("add.rn.f16x2 %0, %1, %2;" : "=r"(d) : "r"(a), "r"(b));
    return d;
}
__device__ __forceinline__ uint32_t mul_h2(uint32_t a, uint32_t b) {
    uint32_t d;
    asm("mul.f16x2 %0, %1, %2;" : "=r"(d) : "r"(a), "r"(b));
    return d;
}

// ======================= HMMA fp16 GEMM (R5 winner, verbatim) =======================
#define G_STRIDE 40
#define G_ASTG   (256 * G_STRIDE)
#define G_BSTG   (128 * G_STRIDE)
#define G_STAGE  (G_ASTG + G_BSTG)
#define G_SMEM   (4 * G_STAGE * 2)

template<bool RELU, bool RES, bool OUTF, bool OUTH>
__global__ __launch_bounds__(256, 1)
void gemm_hmma(const __half* __restrict__ A, const __half* __restrict__ B,
               const float* __restrict__ bias, const float* __restrict__ Rres,
               float* __restrict__ Cf, __half* __restrict__ Ch, int M, int N, int K)
{
    extern __shared__ __half smh[];
    const uint32_t sbase = smem_u32(smh);
    const int tid = threadIdx.x, wid = tid >> 5, lane = tid & 31;
    const int m0 = blockIdx.y * 256, n0 = blockIdx.x * 128;
    const int wm = (wid & 3) * 64, wn = (wid >> 2) * 64;

    float acc[4][8][4];
#pragma unroll
    for (int i = 0; i < 4; i++)
#pragma unroll
        for (int j = 0; j < 8; j++)
#pragma unroll
            for (int e = 0; e < 4; e++) acc[i][j][e] = 0.f;

    const int arow = tid >> 2;
    const int ac   = tid & 3;

    auto load_stage = [&](int kt, int s) {
        const uint32_t sa = sbase + s * G_STAGE * 2;
        const uint32_t sb = sa + G_ASTG * 2;
        const __half* ag = A + (size_t)(m0 + arow) * K + kt * 32 + ac * 8;
#pragma unroll
        for (int i = 0; i < 4; i++) {
            const int row = arow + i * 64;
            CPA16(sa + (row * G_STRIDE + ac * 8) * 2, ag + (size_t)(i * 64) * K);
        }
        const __half* bg = B + (size_t)(n0 + arow) * K + kt * 32 + ac * 8;
#pragma unroll
        for (int i = 0; i < 2; i++) {
            const int row = arow + i * 64;
            CPA16(sb + (row * G_STRIDE + ac * 8) * 2, bg + (size_t)(i * 64) * K);
        }
        CPA_COMMIT();
    };

    const int KT = K >> 5;
    load_stage(0, 0);
    load_stage(1, 1);

    const int aRow = lane & 15, aSel = (lane >> 4) * 8;
    const int bN   = ((lane >> 4) << 3) + (lane & 7);
    const int bSel = ((lane >> 3) & 1) * 8;

    for (int kt = 0; kt < KT; ++kt) {
        const int s = kt & 3;
        if (kt + 2 < KT) {
            load_stage(kt + 2, (kt + 2) & 3);
            CPA_WAIT(2);
        } else if (kt + 1 < KT) {
            CPA_WAIT(1);
        } else {
            CPA_WAIT(0);
        }
        __syncthreads();

        const uint32_t sa0 = sbase + s * G_STAGE * 2;
        const uint32_t sb0 = sa0 + G_ASTG * 2;
#pragma unroll
        for (int ks = 0; ks < 2; ks++) {
            uint32_t a[4][4], b[8][2];
#pragma unroll
            for (int mi = 0; mi < 4; mi++)
                ldsm4(a[mi][0], a[mi][1], a[mi][2], a[mi][3],
                      sa0 + ((wm + mi * 16 + aRow) * G_STRIDE + ks * 16 + aSel) * 2);
#pragma unroll
            for (int nb = 0; nb < 4; nb++) {
                uint32_t r0, r1, r2, r3;
                ldsm4(r0, r1, r2, r3,
                      sb0 + ((wn + nb * 16 + bN) * G_STRIDE + ks * 16 + bSel) * 2);
                b[2 * nb][0] = r0; b[2 * nb][1] = r1;
                b[2 * nb + 1][0] = r2; b[2 * nb + 1][1] = r3;
            }
#pragma unroll
            for (int mi = 0; mi < 4; mi++)
#pragma unroll
                for (int ni = 0; ni < 8; ni++)
                    mma16816(acc[mi][ni], a[mi], b[ni]);
        }
    }

    const int r0 = lane >> 2, c0 = (lane & 3) * 2;
#pragma unroll
    for (int ni = 0; ni < 8; ni++) {
        const int col = n0 + wn + ni * 8 + c0;
        const float2 bv = *(const float2*)(bias + col);
#pragma unroll
        for (int mi = 0; mi < 4; mi++) {
            const int gr0 = m0 + wm + mi * 16 + r0;
            float v0 = acc[mi][ni][0] + bv.x;
            float v1 = acc[mi][ni][1] + bv.y;
            float v2 = acc[mi][ni][2] + bv.x;
            float v3 = acc[mi][ni][3] + bv.y;
            if (RES) {
                float2 ra = *(const float2*)(Rres + (size_t)gr0 * N + col);
                float2 rb = *(const float2*)(Rres + (size_t)(gr0 + 8) * N + col);
                v0 += ra.x; v1 += ra.y; v2 += rb.x; v3 += rb.y;
            }
            if (RELU) {
                v0 = fmaxf(v0, 0.f); v1 = fmaxf(v1, 0.f);
                v2 = fmaxf(v2, 0.f); v3 = fmaxf(v3, 0.f);
            }
            if (OUTF) {
                float2 o0; o0.x = v0; o0.y = v1;
                float2 o1; o1.x = v2; o1.y = v3;
                *(float2*)(Cf + (size_t)gr0 * N + col) = o0;
                *(float2*)(Cf + (size_t)(gr0 + 8) * N + col) = o1;
            }
            if (OUTH) {
                *(uint32_t*)(Ch + (size_t)gr0 * N + col) = packh2(v0, v1);
                *(uint32_t*)(Ch + (size_t)(gr0 + 8) * N + col) = packh2(v2, v3);
            }
        }
    }
}

// ===== Flash attention (R14/R11 verbatim: f16-acc S, f16x2 softmax, l via ones-MMA) =====
#define A_STRIDE 72
#define AT_QMAT  (128 * A_STRIDE)
#define AT_KMAT  (64 * A_STRIDE)
#define A_QOFF   0
#define A_KOFF   AT_QMAT
#define A_VOFF   (AT_QMAT + 2 * AT_KMAT)
#define A_SMEM   ((AT_QMAT + 4 * AT_KMAT) * 2)   // 55296 bytes

__global__ __launch_bounds__(256, 2)
void attn_hmma(const __half* __restrict__ qkv, __half* __restrict__ ctx)
{
    extern __shared__ __half smh[];
    const uint32_t sbase = smem_u32(smh);
    const int tid = threadIdx.x, wid = tid >> 5, lane = tid & 31;
    const int qt = gridDim.x - 1 - blockIdx.x;
    const int h = blockIdx.y, b = blockIdx.z;
    const int q0 = qt * 128;

    const __half* qg = qkv + ((size_t)b * SEQ + q0) * QKVN + h * HDIM;
    const __half* kg = qkv + (size_t)b * SEQ * QKVN + DMODEL + h * HDIM;
    const __half* vg = kg + DMODEL;

#pragma unroll
    for (int i = 0; i < 4; i++) {
        int id = tid + i * 256;
        int row = id >> 3, c = id & 7;
        CPA16(sbase + (A_QOFF + row * A_STRIDE + c * 8) * 2, qg + (size_t)row * QKVN + c * 8);
    }
    auto loadKV = [&](int t, int u) {
        const __half* kt_ = kg + (size_t)(t * 64) * QKVN;
        const __half* vt_ = vg + (size_t)(t * 64) * QKVN;
#pragma unroll
        for (int i = 0; i < 2; i++) {
            int id = tid + i * 256;
            int row = id >> 3, c = id & 7;
            CPA16(sbase + (A_KOFF + u * AT_KMAT + row * A_STRIDE + c * 8) * 2, kt_ + (size_t)row * QKVN + c * 8);
            CPA16(sbase + (A_VOFF + u * AT_KMAT + row * A_STRIDE + c * 8) * 2, vt_ + (size_t)row * QKVN + c * 8);
        }
        CPA_COMMIT();
    };
    loadKV(0, 0);

    uint32_t aQ[4][4];
    float accO[8][4];
    float accL[4];
#pragma unroll
    for (int j = 0; j < 8; j++)
#pragma unroll
        for (int e = 0; e < 4; e++) accO[j][e] = 0.f;
#pragma unroll
    for (int e = 0; e < 4; e++) accL[e] = 0.f;

    const int r0 = lane >> 2, c0 = (lane & 3) * 2;
    const int aRow = lane & 15, aSel = (lane >> 4) * 8;
    const int bN   = ((lane >> 4) << 3) + (lane & 7);
    const int bSel = ((lane >> 3) & 1) * 8;
    const int vK   = (lane & 7) + ((lane >> 3) & 1) * 8;
    const int vN   = (lane >> 4) * 8;

    const uint32_t CLAMP = 0x4B804B80u;                        // f16x2 {15, 15}
    const uint32_t SCLQ  = packh2(0.18033688f, 0.18033688f);   // 0.125 * log2(e)
    const uint32_t NEGINF_LO = 0x0000FC00u;
    const uint32_t NEGINF_HI = 0xFC000000u;
    uint32_t bOnes[2];
    bOnes[0] = 0x3C003C00u; bOnes[1] = 0x3C003C00u;

    const int nt = 2 * qt + 2;
    for (int t = 0; t < nt; t++) {
        const int u = t & 1;
        __syncthreads();
        if (t + 1 < nt) {
            loadKV(t + 1, (t + 1) & 1);
            CPA_WAIT(1);
        } else {
            CPA_WAIT(0);
        }
        __syncthreads();

        if (t == 0) {
#pragma unroll
            for (int ks = 0; ks < 4; ks++) {
                ldsm4(aQ[ks][0], aQ[ks][1], aQ[ks][2], aQ[ks][3],
                      sbase + (A_QOFF + (wid * 16 + aRow) * A_STRIDE + ks * 16 + aSel) * 2);
#pragma unroll
                for (int e = 0; e < 4; e++) aQ[ks][e] = mul_h2(aQ[ks][e], SCLQ);
            }
        }

        uint32_t scP[8][2];
#pragma unroll
        for (int j = 0; j < 8; j++) { scP[j][0] = 0u; scP[j][1] = 0u; }

        const uint32_t kb = sbase + (A_KOFF + u * AT_KMAT) * 2;
#pragma unroll
        for (int ks = 0; ks < 4; ks++) {
            uint32_t bK[8][2];
#pragma unroll
            for (int nb = 0; nb < 4; nb++) {
                uint32_t x0, x1, x2, x3;
                ldsm4(x0, x1, x2, x3, kb + ((nb * 16 + bN) * A_STRIDE + ks * 16 + bSel) * 2);
                bK[2 * nb][0] = x0; bK[2 * nb][1] = x1;
                bK[2 * nb + 1][0] = x2; bK[2 * nb + 1][1] = x3;
            }
#pragma unroll
            for (int j = 0; j < 8; j++)
                mma16816h(scP[j], aQ[ks], bK[j]);
        }

        if (t >= 2 * qt) {
            const int rg0 = q0 + wid * 16 + r0;
#pragma unroll
            for (int j = 0; j < 8; j++) {
                const int kcol = t * 64 + j * 8 + c0;
                uint32_t m0 = (kcol > rg0 ? NEGINF_LO : 0u) | (kcol + 1 > rg0 ? NEGINF_HI : 0u);
                uint32_t m1 = (kcol > rg0 + 8 ? NEGINF_LO : 0u) | (kcol + 1 > rg0 + 8 ? NEGINF_HI : 0u);
                if (m0) scP[j][0] = add_h2(scP[j][0], m0);
                if (m1) scP[j][1] = add_h2(scP[j][1], m1);
            }
        }

#pragma unroll
        for (int j = 0; j < 8; j++) {
            scP[j][0] = ex2_h2(min_h2(scP[j][0], CLAMP));
            scP[j][1] = ex2_h2(min_h2(scP[j][1], CLAMP));
        }

        const uint32_t vb = sbase + (A_VOFF + u * AT_KMAT) * 2;
#pragma unroll
        for (int k2 = 0; k2 < 4; k2++) {
            uint32_t aP[4];
            aP[0] = scP[2 * k2][0];     aP[1] = scP[2 * k2][1];
            aP[2] = scP[2 * k2 + 1][0]; aP[3] = scP[2 * k2 + 1][1];
            uint32_t bV[8][2];
#pragma unroll
            for (int nb = 0; nb < 4; nb++) {
                uint32_t x0, x1, x2, x3;
                ldsm4t(x0, x1, x2, x3, vb + ((k2 * 16 + vK) * A_STRIDE + nb * 16 + vN) * 2);
                bV[2 * nb][0] = x0; bV[2 * nb][1] = x1;
                bV[2 * nb + 1][0] = x2; bV[2 * nb + 1][1] = x3;
            }
#pragma unroll
            for (int j = 0; j < 8; j++)
                mma16816(accO[j], aP, bV[j]);
            mma16816(accL, aP, bOnes);
        }
    }

    const float inv0 = 1.f / accL[0], inv1 = 1.f / accL[2];
    const size_t grow = (size_t)b * SEQ + q0 + wid * 16 + r0;
#pragma unroll
    for (int j = 0; j < 8; j++) {
        const int col = h * HDIM + j * 8 + c0;
        *(uint32_t*)(ctx + grow * DMODEL + col)       = packh2(accO[j][0] * inv0, accO[j][1] * inv0);
        *(uint32_t*)(ctx + (grow + 8) * DMODEL + col) = packh2(accO[j][2] * inv1, accO[j][3] * inv1);
    }
}

// ======================= fused fp32 -> fp16 convert (all 5 tensors, one launch) ==========
__global__ __launch_bounds__(256)
void f2h_five(const float* __restrict__ s0, __half* __restrict__ d0, int n0,
              const float* __restrict__ s1, __half* __restrict__ d1, int n1,
              const float* __restrict__ s2, __half* __restrict__ d2, int n2,
              const float* __restrict__ s3, __half* __restrict__ d3, int n3,
              const float* __restrict__ s4, __half* __restrict__ d4, int n4)
{
    int i = blockIdx.x * 256 + threadIdx.x;
    const float* s; __half* d;
    if (i < n0)      { s = s0; d = d0; }
    else if ((i -= n0) < n1) { s = s1; d = d1; }
    else if ((i -= n1) < n2) { s = s2; d = d2; }
    else if ((i -= n2) < n3) { s = s3; d = d3; }
    else if ((i -= n3) < n4) { s = s4; d = d4; }
    else return;
    float4 v = ((const float4*)s)[i];
    ((uint32_t*)d)[2 * i]     = packh2(v.x, v.y);
    ((uint32_t*)d)[2 * i + 1] = packh2(v.z, v.w);
}

// ======================= LayerNorm: one warp per row, no smem, no barriers ==============
template<bool OUTH>
__global__ __launch_bounds__(256)
void ln_kernel(const float* __restrict__ y, const float* __restrict__ g,
               const float* __restrict__ b, float* __restrict__ out, __half* __restrict__ oh)
{
    const int wid = threadIdx.x >> 5, lane = threadIdx.x & 31;
    const int row = blockIdx.x * 8 + wid;

    const float* yr = y + (size_t)row * DMODEL;
    float4 v[4];
#pragma unroll
    for (int c = 0; c < 4; c++)
        v[c] = *(const float4*)(yr + c * 128 + lane * 4);

    float s = 0.f;
#pragma unroll
    for (int c = 0; c < 4; c++) s += v[c].x + v[c].y + v[c].z + v[c].w;
#pragma unroll
    for (int o = 16; o; o >>= 1) s += __shfl_xor_sync(0xffffffffu, s, o);
    const float mu = s * (1.f / DMODEL);

    float q = 0.f;
#pragma unroll
    for (int c = 0; c < 4; c++) {
        v[c].x -= mu; v[c].y -= mu; v[c].z -= mu; v[c].w -= mu;
        q += v[c].x * v[c].x + v[c].y * v[c].y + v[c].z * v[c].z + v[c].w * v[c].w;
    }
#pragma unroll
    for (int o = 16; o; o >>= 1) q += __shfl_xor_sync(0xffffffffu, q, o);
    const float r = rsqrtf(q * (1.f / DMODEL) + 1e-5f);

#pragma unroll
    for (int c = 0; c < 4; c++) {
        const int col = c * 128 + lane * 4;
        float4 gg = *(const float4*)(g + col);
        float4 bb = *(const float4*)(b + col);
        float o0 = v[c].x * r * gg.x + bb.x;
        float o1 = v[c].y * r * gg.y + bb.y;
        float o2 = v[c].z * r * gg.z + bb.z;
        float o3 = v[c].w * r * gg.w + bb.w;
        float4 ov; ov.x = o0; ov.y = o1; ov.z = o2; ov.w = o3;
        *(float4*)(out + (size_t)row * DMODEL + col) = ov;
        if (OUTH) {
            size_t ofs = (size_t)row * DMODEL + col;
            *(uint32_t*)(oh + ofs)     = packh2(o0, o1);
            *(uint32_t*)(oh + ofs + 2) = packh2(o2, o3);
        }
    }
}

// =================================== launch ===================================
extern "C" void kernel_launch(void* const* d_in, const int* in_sizes, int n_in,
                              void* d_out, int out_size)
{
    const float* x    = (const float*)d_in[0];
    const float* Wqkv = (const float*)d_in[1];
    const float* bqkv = (const float*)d_in[2];
    const float* Wo   = (const float*)d_in[3];
    const float* bo   = (const float*)d_in[4];
    const float* W1   = (const float*)d_in[5];
    const float* b1   = (const float*)d_in[6];
    const float* W2   = (const float*)d_in[7];
    const float* b2   = (const float*)d_in[8];
    const float* g1   = (const float*)d_in[9];
    const float* bn1  = (const float*)d_in[10];
    const float* g2   = (const float*)d_in[11];
    const float* bn2  = (const float*)d_in[12];
    float* out = (float*)d_out;

    __half *p_x16, *p_qkv16, *p_ctx16, *p_x1h, *p_h16;
    __half *p_wqkv, *p_wo, *p_w1, *p_w2;
    float *p_y1, *p_x1;
    cudaGetSymbolAddress((void**)&p_x16,   g_x16);
    cudaGetSymbolAddress((void**)&p_qkv16, g_qkv16);
    cudaGetSymbolAddress((void**)&p_ctx16, g_ctx16);
    cudaGetSymbolAddress((void**)&p_x1h,   g_x1h);
    cudaGetSymbolAddress((void**)&p_h16,   g_h16);
    cudaGetSymbolAddress((void**)&p_y1,    g_y1);
    cudaGetSymbolAddress((void**)&p_x1,    g_x1);
    cudaGetSymbolAddress((void**)&p_wqkv,  g_wqkv16);
    cudaGetSymbolAddress((void**)&p_wo,    g_wo16);
    cudaGetSymbolAddress((void**)&p_w1,    g_w1_16);
    cudaGetSymbolAddress((void**)&p_w2,    g_w2_16);

    cudaFuncSetAttribute(gemm_hmma<false, false, false, true>, cudaFuncAttributeMaxDynamicSharedMemorySize, G_SMEM);
    cudaFuncSetAttribute(gemm_hmma<false, true,  true,  false>, cudaFuncAttributeMaxDynamicSharedMemorySize, G_SMEM);
    cudaFuncSetAttribute(gemm_hmma<true,  false, false, true>, cudaFuncAttributeMaxDynamicSharedMemorySize, G_SMEM);
    cudaFuncSetAttribute(attn_hmma, cudaFuncAttributeMaxDynamicSharedMemorySize, A_SMEM);

    const int M = MROWS;
    const int c0 = M * DMODEL / 4, c1 = QKVN * DMODEL / 4, c2 = DMODEL * DMODEL / 4;
    const int c3 = FFDIM * DMODEL / 4, c4 = DMODEL * FFDIM / 4;

    // [0] all fp32 -> fp16 conversions in one launch
    f2h_five<<<(c0 + c1 + c2 + c3 + c4 + 255) / 256, 256>>>(
        x, p_x16, c0, Wqkv, p_wqkv, c1, Wo, p_wo, c2, W1, p_w1, c3, W2, p_w2, c4);

    // [1] QKV projection -> qkv fp16
    gemm_hmma<false, false, false, true><<<dim3(QKVN / 128, M / 256), 256, G_SMEM>>>(
        p_x16, p_wqkv, bqkv, nullptr, nullptr, p_qkv16, M, QKVN, DMODEL);

    // [2] causal flash attention -> ctx fp16
    attn_hmma<<<dim3(SEQ / 128, NHEADS, BATCH), 256, A_SMEM>>>(p_qkv16, p_ctx16);

    // [3] out proj + residual(x) -> y1 fp32
    gemm_hmma<false, true, true, false><<<dim3(DMODEL / 128, M / 256), 256, G_SMEM>>>(
        p_ctx16, p_wo, bo, x, p_y1, nullptr, M, DMODEL, DMODEL);

    // [4] LN1 -> x1 fp32 + fp16
    ln_kernel<true><<<M / 8, 256>>>(p_y1, g1, bn1, p_x1, p_x1h);

    // [5] FFN up + ReLU -> h fp16
    gemm_hmma<true, false, false, true><<<dim3(FFDIM / 128, M / 256), 256, G_SMEM>>>(
        p_x1h, p_w1, b1, nullptr, nullptr, p_h16, M, FFDIM, DMODEL);

    // [6] FFN down + residual(x1) -> y1 fp32
    gemm_hmma<false, true, true, false><<<dim3(DMODEL / 128, M / 256), 256, G_SMEM>>>(
        p_h16, p_w2, b2, p_x1, p_y1, nullptr, M, DMODEL, FFDIM);

    // [7] LN2 -> out
    ln_kernel<false><<<M / 8, 256>>>(p_y1, g2, bn2, out, nullptr);
}